// round 1
// baseline (speedup 1.0000x reference)
#include <cuda_runtime.h>
#include <cuda_bf16.h>
#include <math.h>

// ---------------- problem constants ----------------
#define LN      256      // leaves
#define MEMD    256      // memory dim
#define IND     300      // input dim
#define MTOT    511      // total tree nodes (2L-1)
#define HIDD    128
#define NCLS    5

// ---------------- device scratch (no cudaMalloc allowed) ----------------
__device__ float  g_WxT[IND * 768];          // W_ioux^T  [t][j]
__device__ float4 g_Wpack[MEMD * MEMD];      // {Wh_i, Wh_o, Wh_u, Wf} at [t][j]
__device__ float  g_W1T[MEMD * MEMD];        // W_attnh[:, :256]^T   [e][d]
__device__ float  g_W2T[MEMD * MEMD];        // W_attnh[:, 256:]^T   [e][d]
__device__ float  g_mat[2][MTOT * MEMD];     // h of no-attn trees (side 0=L,1=R)
__device__ float  g_c  [2][MTOT * MEMD];     // c of no-attn trees
__device__ float  g_pb [2][MTOT * MEMD];     // mat @ W2^T + b_attnh, per mat-side
__device__ float  g_hA [2][MTOT * MEMD];     // attended h per pass (0=pass2, 1=pass4)
__device__ float  g_cA [2][MTOT * MEMD];     // attended-pass c
__device__ float  g_hPre[2][MTOT * MEMD];    // pre-attention h per pass
__device__ float  g_scores[2][LN * MTOT];    // raw attention scores, row-local index

__device__ __forceinline__ float sigm_acc(float x) { return 1.0f / (1.0f + expf(-x)); }
__device__ __forceinline__ float tanh_fast(float x) {
    float y; asm("tanh.approx.f32 %0, %1;" : "=f"(y) : "f"(x)); return y;
}

// ---------------- prep: build transposed / packed weights ----------------
__global__ void prep_kernel(const float* __restrict__ W_ioux,
                            const float* __restrict__ W_iouh,
                            const float* __restrict__ W_fh,
                            const float* __restrict__ W_attnh) {
    int i = blockIdx.x * blockDim.x + threadIdx.x;
    const int N1 = IND * 768;          // WxT
    const int N2 = MEMD * MEMD;        // Wpack
    const int N3 = MEMD * MEMD;        // W1T
    const int N4 = MEMD * MEMD;        // W2T
    if (i < N1) {
        int t = i / 768, j = i % 768;
        g_WxT[i] = W_ioux[j * IND + t];
    } else if (i < N1 + N2) {
        int e = i - N1; int t = e >> 8, j = e & 255;
        g_Wpack[e] = make_float4(W_iouh[j * MEMD + t],
                                 W_iouh[(256 + j) * MEMD + t],
                                 W_iouh[(512 + j) * MEMD + t],
                                 W_fh[j * MEMD + t]);
    } else if (i < N1 + N2 + N3) {
        int e = i - N1 - N2; int ee = e >> 8, d = e & 255;
        g_W1T[e] = W_attnh[d * 512 + ee];
    } else if (i < N1 + N2 + N3 + N4) {
        int e = i - N1 - N2 - N3; int ee = e >> 8, d = e & 255;
        g_W2T[e] = W_attnh[d * 512 + 256 + ee];
    }
}

// ---------------- leaf: gather + IOU GEMM + gates (both sides) ----------------
// grid 64 = side(2) x group(32), 8 rows/group; block 768 (one thread per iou col)
__global__ void leaf_kernel(const int* __restrict__ l_idx, const int* __restrict__ r_idx,
                            const float* __restrict__ emb,
                            const float* __restrict__ b_ioux, const float* __restrict__ b_iouh) {
    int side = blockIdx.x >> 5;
    int grp  = blockIdx.x & 31;
    const int* idx = side ? r_idx : l_idx;
    __shared__ float xs[8][IND];
    __shared__ float iou_s[8][768];
    int tid = threadIdx.x;
    for (int e = tid; e < 8 * IND; e += 768) {
        int r = e / IND, t = e - r * IND;
        xs[r][t] = emb[(long)idx[grp * 8 + r] * IND + t];
    }
    __syncthreads();
    float acc[8];
    float bias = b_ioux[tid] + b_iouh[tid];
#pragma unroll
    for (int r = 0; r < 8; r++) acc[r] = bias;
    for (int t = 0; t < IND; t++) {
        float w = g_WxT[t * 768 + tid];
#pragma unroll
        for (int r = 0; r < 8; r++) acc[r] = fmaf(w, xs[r][t], acc[r]);
    }
#pragma unroll
    for (int r = 0; r < 8; r++) iou_s[r][tid] = acc[r];
    __syncthreads();
    for (int e = tid; e < 8 * 256; e += 768) {
        int r = e >> 8, j = e & 255;
        float iv = sigm_acc(iou_s[r][j]);
        float ov = sigm_acc(iou_s[r][256 + j]);
        float uv = tanhf(iou_s[r][512 + j]);
        float c = iv * uv;
        float h = ov * tanhf(c);
        int row = grp * 8 + r;
        g_c[side][row * MEMD + j]   = c;
        g_mat[side][row * MEMD + j] = h;
    }
}

// ---------------- tree level (shared by no-attn trees and attended passes) ----
// mode 0: no-attn, blockIdx.y = side; mode 1: attended, blockIdx.y = pass
template <int RT>
__global__ void tree_level_kernel(int mode, int lev, int off_prev, int off, int k,
                                  const float* __restrict__ b_iouh,
                                  const float* __restrict__ b_fh) {
    int y = blockIdx.y;
    const float *hsrc, *csrc;
    float *hdst, *cdst;
    if (mode == 0) { hsrc = g_mat[y]; csrc = g_c[y]; hdst = g_mat[y]; cdst = g_c[y]; }
    else {
        int xside = (y == 0) ? 1 : 0;
        hsrc = g_hA[y];
        csrc = (lev == 1) ? g_c[xside] : g_cA[y];
        hdst = g_hPre[y]; cdst = g_cA[y];
    }
    int nbase = blockIdx.x * RT;
    if (nbase >= k) return;
    __shared__ float h0[RT][MEMD], h1[RT][MEMD], hs[RT][MEMD];
    int tid = threadIdx.x;
#pragma unroll
    for (int r = 0; r < RT; r++) {
        int ch = (off_prev + 2 * (nbase + r)) * MEMD;
        float a = hsrc[ch + tid], b = hsrc[ch + MEMD + tid];
        h0[r][tid] = a; h1[r][tid] = b; hs[r][tid] = a + b;
    }
    __syncthreads();
    float ai[RT], ao[RT], au[RT], af0[RT], af1[RT];
#pragma unroll
    for (int r = 0; r < RT; r++) { ai[r]=0; ao[r]=0; au[r]=0; af0[r]=0; af1[r]=0; }
    for (int t = 0; t < MEMD; t++) {
        float4 w = g_Wpack[t * MEMD + tid];
#pragma unroll
        for (int r = 0; r < RT; r++) {
            ai[r]  = fmaf(w.x, hs[r][t], ai[r]);
            ao[r]  = fmaf(w.y, hs[r][t], ao[r]);
            au[r]  = fmaf(w.z, hs[r][t], au[r]);
            af0[r] = fmaf(w.w, h0[r][t], af0[r]);
            af1[r] = fmaf(w.w, h1[r][t], af1[r]);
        }
    }
    float bi = b_iouh[tid], bo = b_iouh[256 + tid], bu = b_iouh[512 + tid], bf = b_fh[tid];
#pragma unroll
    for (int r = 0; r < RT; r++) {
        int node = nbase + r;
        float iv = sigm_acc(ai[r] + bi);
        float ov = sigm_acc(ao[r] + bo);
        float uv = tanhf(au[r] + bu);
        float f0 = sigm_acc(af0[r] + bf);
        float f1 = sigm_acc(af1[r] + bf);
        int ch = (off_prev + 2 * node) * MEMD;
        float c = iv * uv + f0 * csrc[ch + tid] + f1 * csrc[ch + MEMD + tid];
        float h = ov * tanhf(c);
        cdst[(off + node) * MEMD + tid] = c;
        hdst[(off + node) * MEMD + tid] = h;
    }
}

// ---------------- proj: pb[side][m] = mat[side][m] @ W2^T + b_attnh ----------
__global__ void proj_kernel(const float* __restrict__ b_attnh) {
    int side = blockIdx.y;
    int mbase = blockIdx.x * 8;
    __shared__ float ms[8][MEMD];
    int tid = threadIdx.x;
#pragma unroll
    for (int r = 0; r < 8; r++) {
        int m = min(mbase + r, MTOT - 1);
        ms[r][tid] = g_mat[side][m * MEMD + tid];
    }
    __syncthreads();
    float acc[8];
    float ba = b_attnh[tid];
#pragma unroll
    for (int r = 0; r < 8; r++) acc[r] = ba;
    for (int e = 0; e < MEMD; e++) {
        float w = g_W2T[e * MEMD + tid];
#pragma unroll
        for (int r = 0; r < 8; r++) acc[r] = fmaf(w, ms[r][e], acc[r]);
    }
#pragma unroll
    for (int r = 0; r < 8; r++)
        if (mbase + r < MTOT) g_pb[side][(mbase + r) * MEMD + tid] = acc[r];
}

// ---------------- attention scores ------------------------------------------
// grid (S, ceil(k/RS), 2passes); block 256 (8 warps, warp-per-key)
template <int RS>
__global__ void scores_kernel(int leaf, int roff, int k, int chunk,
                              const float* __restrict__ Wa) {
    int p = blockIdx.z;
    int matside = (p == 0) ? 0 : 1;
    int xside = 1 - matside;
    int nbase = blockIdx.y * RS;
    if (nbase >= k) return;
    int m0 = blockIdx.x * chunk;
    int m1 = min(MTOT, m0 + chunk);
    const float* hsrc = leaf ? g_mat[xside] : g_hPre[p];
    __shared__ float hsm[RS][MEMD];
    __shared__ float hp[RS][MEMD];
    __shared__ float sWa[MEMD];
    int tid = threadIdx.x;
    sWa[tid] = Wa[tid];
#pragma unroll
    for (int r = 0; r < RS; r++) hsm[r][tid] = hsrc[(roff + nbase + r) * MEMD + tid];
    __syncthreads();
    float acc[RS];
#pragma unroll
    for (int r = 0; r < RS; r++) acc[r] = 0.f;
    for (int e = 0; e < MEMD; e++) {
        float w = g_W1T[e * MEMD + tid];
#pragma unroll
        for (int r = 0; r < RS; r++) acc[r] = fmaf(w, hsm[r][e], acc[r]);
    }
#pragma unroll
    for (int r = 0; r < RS; r++) hp[r][tid] = acc[r];
    __syncthreads();
    int warp = tid >> 5, lane = tid & 31;
    for (int m = m0 + warp; m < m1; m += 8) {
        const float* pbrow = &g_pb[matside][m * MEMD];
        float sacc[RS];
#pragma unroll
        for (int r = 0; r < RS; r++) sacc[r] = 0.f;
#pragma unroll
        for (int dd = 0; dd < 8; dd++) {
            int d = dd * 32 + lane;
            float pb = pbrow[d];
            float wv = sWa[d];
#pragma unroll
            for (int r = 0; r < RS; r++) {
                float t = tanh_fast(hp[r][d] + pb);
                sacc[r] = fmaf(t, wv, sacc[r]);
            }
        }
#pragma unroll
        for (int r = 0; r < RS; r++) {
            float v = sacc[r];
#pragma unroll
            for (int o = 16; o; o >>= 1) v += __shfl_xor_sync(0xffffffffu, v, o);
            if (lane == 0) g_scores[p][(nbase + r) * MTOT + m] = v;
        }
    }
}

// ---------------- softmax + combine: h_out = sum_m(1-s_m)mat_m + h -----------
template <int RC>
__global__ void combine_kernel(int leaf, int roff, int k) {
    int p = blockIdx.y;
    int matside = (p == 0) ? 0 : 1;
    int xside = 1 - matside;
    int nbase = blockIdx.x * RC;
    if (nbase >= k) return;
    const float* hsrc = leaf ? g_mat[xside] : g_hPre[p];
    __shared__ float es[RC][512];
    __shared__ float hsm[RC][MEMD];
    __shared__ float red[256];
    __shared__ float ssum[RC];
    int tid = threadIdx.x;
#pragma unroll
    for (int r = 0; r < RC; r++) hsm[r][tid] = hsrc[(roff + nbase + r) * MEMD + tid];
    for (int r = 0; r < RC; r++) {
        const float* sr = &g_scores[p][(nbase + r) * MTOT];
        float e0 = sr[tid];
        float e1 = (tid < 255) ? sr[256 + tid] : -1e30f;
        red[tid] = fmaxf(e0, e1);
        __syncthreads();
        for (int s = 128; s; s >>= 1) { if (tid < s) red[tid] = fmaxf(red[tid], red[tid + s]); __syncthreads(); }
        float mx = red[0];
        __syncthreads();
        float x0 = __expf(e0 - mx);
        float x1 = (tid < 255) ? __expf(e1 - mx) : 0.f;
        es[r][tid] = x0; es[r][256 + tid] = x1;
        red[tid] = x0 + x1;
        __syncthreads();
        for (int s = 128; s; s >>= 1) { if (tid < s) red[tid] += red[tid + s]; __syncthreads(); }
        if (tid == 0) ssum[r] = red[0];
        __syncthreads();
    }
    int q = tid & 63, strip = tid >> 6;
    const float4* mat4 = (const float4*)g_mat[matside];
    float4 a1 = make_float4(0, 0, 0, 0);
    float4 a2[RC];
#pragma unroll
    for (int r = 0; r < RC; r++) a2[r] = make_float4(0, 0, 0, 0);
    for (int m = strip; m < MTOT; m += 4) {
        float4 mv = mat4[m * 64 + q];
        a1.x += mv.x; a1.y += mv.y; a1.z += mv.z; a1.w += mv.w;
#pragma unroll
        for (int r = 0; r < RC; r++) {
            float e = es[r][m];
            a2[r].x = fmaf(e, mv.x, a2[r].x);
            a2[r].y = fmaf(e, mv.y, a2[r].y);
            a2[r].z = fmaf(e, mv.z, a2[r].z);
            a2[r].w = fmaf(e, mv.w, a2[r].w);
        }
    }
    __shared__ float4 sp1[4][64];
    __shared__ float4 sp2[4][RC][64];
    sp1[strip][q] = a1;
#pragma unroll
    for (int r = 0; r < RC; r++) sp2[strip][r][q] = a2[r];
    __syncthreads();
    if (strip == 0) {
        float4 t1 = sp1[0][q];
        t1.x += sp1[1][q].x + sp1[2][q].x + sp1[3][q].x;
        t1.y += sp1[1][q].y + sp1[2][q].y + sp1[3][q].y;
        t1.z += sp1[1][q].z + sp1[2][q].z + sp1[3][q].z;
        t1.w += sp1[1][q].w + sp1[2][q].w + sp1[3][q].w;
#pragma unroll
        for (int r = 0; r < RC; r++) {
            float4 t2 = sp2[0][r][q];
            t2.x += sp2[1][r][q].x + sp2[2][r][q].x + sp2[3][r][q].x;
            t2.y += sp2[1][r][q].y + sp2[2][r][q].y + sp2[3][r][q].y;
            t2.z += sp2[1][r][q].z + sp2[2][r][q].z + sp2[3][r][q].z;
            t2.w += sp2[1][r][q].w + sp2[2][r][q].w + sp2[3][r][q].w;
            float inv = 1.0f / ssum[r];
            int base = (roff + nbase + r) * MEMD + 4 * q;
            float o0 = t1.x - t2.x * inv + hsm[r][4 * q + 0];
            float o1 = t1.y - t2.y * inv + hsm[r][4 * q + 1];
            float o2 = t1.z - t2.z * inv + hsm[r][4 * q + 2];
            float o3 = t1.w - t2.w * inv + hsm[r][4 * q + 3];
            g_hA[p][base + 0] = o0;
            g_hA[p][base + 1] = o1;
            g_hA[p][base + 2] = o2;
            g_hA[p][base + 3] = o3;
        }
    }
}

// ---------------- final classifier -------------------------------------------
__global__ void final_kernel(const float* __restrict__ W_wh, const float* __restrict__ b_wh,
                             const float* __restrict__ W_wp, const float* __restrict__ b_wp,
                             float* __restrict__ out) {
    __shared__ float v[512];
    __shared__ float hid[HIDD];
    int tid = threadIdx.x;  // 256
    float lh = tanhf(g_mat[0][510 * MEMD + tid] + g_hA[1][510 * MEMD + tid]);
    float rh = tanhf(g_hA[0][510 * MEMD + tid] + g_mat[1][510 * MEMD + tid]);
    v[tid] = lh * rh;
    v[256 + tid] = fabsf(lh - rh);
    __syncthreads();
    if (tid < HIDD) {
        float a = b_wh[tid];
        for (int e = 0; e < 512; e++) a = fmaf(W_wh[tid * 512 + e], v[e], a);
        hid[tid] = sigm_acc(a);
    }
    __syncthreads();
    if (tid < 32) {
        float z[NCLS];
#pragma unroll
        for (int c = 0; c < NCLS; c++) {
            float a = 0.f;
            for (int e = tid; e < HIDD; e += 32) a = fmaf(W_wp[c * HIDD + e], hid[e], a);
#pragma unroll
            for (int o = 16; o; o >>= 1) a += __shfl_xor_sync(0xffffffffu, a, o);
            z[c] = a + b_wp[c];
        }
        if (tid == 0) {
            float mx = z[0];
#pragma unroll
            for (int c = 1; c < NCLS; c++) mx = fmaxf(mx, z[c]);
            float s = 0.f;
#pragma unroll
            for (int c = 0; c < NCLS; c++) s += expf(z[c] - mx);
            float ls = logf(s);
#pragma unroll
            for (int c = 0; c < NCLS; c++) out[c] = z[c] - mx - ls;
        }
    }
}

// ---------------- host orchestration -----------------------------------------
extern "C" void kernel_launch(void* const* d_in, const int* in_sizes, int n_in,
                              void* d_out, int out_size) {
    const int*   l_idx   = (const int*)d_in[0];
    const int*   r_idx   = (const int*)d_in[1];
    const float* emb     = (const float*)d_in[2];
    const float* W_ioux  = (const float*)d_in[3];
    const float* b_ioux  = (const float*)d_in[4];
    const float* W_iouh  = (const float*)d_in[5];
    const float* b_iouh  = (const float*)d_in[6];
    // d_in[7] = W_fx, d_in[8] = b_fx : unused by the reference
    const float* W_fh    = (const float*)d_in[9];
    const float* b_fh    = (const float*)d_in[10];
    const float* Wa      = (const float*)d_in[11];
    const float* W_attnh = (const float*)d_in[12];
    const float* b_attnh = (const float*)d_in[13];
    const float* W_wh    = (const float*)d_in[14];
    const float* b_wh    = (const float*)d_in[15];
    const float* W_wp    = (const float*)d_in[16];
    const float* b_wp    = (const float*)d_in[17];
    float* out = (float*)d_out;

    const int total_prep = IND * 768 + 3 * MEMD * MEMD;
    prep_kernel<<<(total_prep + 255) / 256, 256>>>(W_ioux, W_iouh, W_fh, W_attnh);
    leaf_kernel<<<64, 768>>>(l_idx, r_idx, emb, b_ioux, b_iouh);

    int off[9] = {0, 256, 384, 448, 480, 496, 504, 508, 510};

    // no-attention trees (sides L and R together)
    for (int lev = 1; lev <= 8; lev++) {
        int k = LN >> lev;
        if (k >= 32)
            tree_level_kernel<4><<<dim3(k / 4, 2), 256>>>(0, lev, off[lev - 1], off[lev], k, b_iouh, b_fh);
        else
            tree_level_kernel<1><<<dim3(k, 2), 256>>>(0, lev, off[lev - 1], off[lev], k, b_iouh, b_fh);
    }

    proj_kernel<<<dim3(64, 2), 256>>>(b_attnh);

    // attended leaf (pass2: R attends matL; pass4: L attends matR)
    scores_kernel<4><<<dim3(1, 64, 2), 256>>>(1, 0, LN, MTOT, Wa);
    combine_kernel<4><<<dim3(64, 2), 256>>>(1, 0, LN);

    for (int lev = 1; lev <= 8; lev++) {
        int k = LN >> lev;
        if (k >= 32)
            tree_level_kernel<4><<<dim3(k / 4, 2), 256>>>(1, lev, off[lev - 1], off[lev], k, b_iouh, b_fh);
        else
            tree_level_kernel<1><<<dim3(k, 2), 256>>>(1, lev, off[lev - 1], off[lev], k, b_iouh, b_fh);

        int S = (k >= 64) ? 1 : (k == 32 ? 2 : (k == 16 ? 4 : (k == 8 ? 8 : (k == 4 ? 16 : (k == 2 ? 32 : 64)))));
        int chunk = (MTOT + S - 1) / S;
        if (k >= 128)
            scores_kernel<2><<<dim3(S, k / 2, 2), 256>>>(0, off[lev], k, chunk, Wa);
        else
            scores_kernel<1><<<dim3(S, k, 2), 256>>>(0, off[lev], k, chunk, Wa);

        if (k >= 4)
            combine_kernel<4><<<dim3(k / 4, 2), 256>>>(0, off[lev], k);
        else if (k == 2)
            combine_kernel<2><<<dim3(1, 2), 256>>>(0, off[lev], k);
        else
            combine_kernel<1><<<dim3(1, 2), 256>>>(0, off[lev], k);
    }

    final_kernel<<<1, 256>>>(W_wh, b_wh, W_wp, b_wp, out);
}

// round 2
// speedup vs baseline: 1.2265x; 1.2265x over previous
#include <cuda_runtime.h>
#include <cuda_bf16.h>
#include <math.h>

// ---------------- problem constants ----------------
#define LN      256
#define MEMD    256
#define IND     300
#define MTOT    511
#define HIDD    128
#define NCLS    5
#define NBLK    296

// ---------------- device scratch ----------------
__device__ float  g_WxT[IND * 768];
__device__ float4 g_Wpack[MEMD * MEMD];
__device__ float  g_W1T[MEMD * MEMD];
__device__ float  g_W2T[MEMD * MEMD];
__device__ float  g_iou[512 * 768];
__device__ float  g_mat[2][MTOT * MEMD];
__device__ float  g_c  [2][MTOT * MEMD];
__device__ float  g_pb [2][MTOT * MEMD];
__device__ float  g_colsum[2][MEMD];
__device__ float  g_hA [2][MTOT * MEMD];
__device__ float  g_cA [2][MTOT * MEMD];
__device__ float  g_hPre[2][MTOT * MEMD];
__device__ float  g_scores[2][MTOT * MTOT];
__device__ int    g_bar[64];

__device__ __forceinline__ float sigm_acc(float x) { return 1.0f / (1.0f + expf(-x)); }
__device__ __forceinline__ float tanh_fast(float x) {
    float y; asm("tanh.approx.f32 %0, %1;" : "=f"(y) : "f"(x)); return y;
}

// ---------------- global software barrier ----------------
__device__ __forceinline__ void gbar(int id) {
    __syncthreads();
    if (threadIdx.x == 0) {
        __threadfence();
        atomicAdd(&g_bar[id], 1);
        while (*((volatile int*)&g_bar[id]) < NBLK) { }
        __threadfence();
    }
    __syncthreads();
}

__global__ void reset_kernel() {
    if (threadIdx.x < 64) g_bar[threadIdx.x] = 0;
}

// ================= stages =================

__device__ void st_prep(int bid, int tid,
                        const float* __restrict__ W_ioux, const float* __restrict__ W_iouh,
                        const float* __restrict__ W_fh,   const float* __restrict__ W_attnh) {
    const int N1 = IND * 768, N2 = MEMD * MEMD, N3 = MEMD * MEMD, N4 = MEMD * MEMD;
    for (int i = bid * 256 + tid; i < N1 + N2 + N3 + N4; i += NBLK * 256) {
        if (i < N1) {
            int t = i / 768, j = i - t * 768;
            g_WxT[i] = W_ioux[j * IND + t];
        } else if (i < N1 + N2) {
            int e = i - N1; int t = e >> 8, j = e & 255;
            g_Wpack[e] = make_float4(W_iouh[j * MEMD + t],
                                     W_iouh[(256 + j) * MEMD + t],
                                     W_iouh[(512 + j) * MEMD + t],
                                     W_fh[j * MEMD + t]);
        } else if (i < N1 + N2 + N3) {
            int e = i - N1 - N2; int ee = e >> 8, d = e & 255;
            g_W1T[e] = W_attnh[d * 512 + ee];
        } else {
            int e = i - N1 - N2 - N3; int ee = e >> 8, d = e & 255;
            g_W2T[e] = W_attnh[d * 512 + 256 + ee];
        }
    }
}

// leaf GEMM: 192 blocks = 64 row-groups (8 rows) x 3 col-parts (256 cols)
__device__ void st_leafgemm(int bid, int tid, char* sm,
                            const int* __restrict__ l_idx, const int* __restrict__ r_idx,
                            const float* __restrict__ emb,
                            const float* __restrict__ b_ioux, const float* __restrict__ b_iouh) {
    if (bid >= 192) return;
    float* xs = (float*)sm;                 // 8*300
    int* sidx = (int*)(sm + 2400 * 4);      // 8 ints
    int rowgrp = bid & 63;
    int part = bid >> 6;
    if (tid < 8) {
        int grow = rowgrp * 8 + tid;
        sidx[tid] = (grow >= 256) ? r_idx[grow - 256] : l_idx[grow];
    }
    __syncthreads();
    for (int e = tid; e < 8 * IND; e += 256) {
        int rr = e / IND, t = e - rr * IND;
        xs[e] = emb[(long)sidx[rr] * IND + t];
    }
    __syncthreads();
    int col = part * 256 + tid;
    float bias = b_ioux[col] + b_iouh[col];
    float acc[8];
#pragma unroll
    for (int r = 0; r < 8; r++) acc[r] = bias;
#pragma unroll 4
    for (int t = 0; t < IND; t++) {
        float w = g_WxT[t * 768 + col];
#pragma unroll
        for (int r = 0; r < 8; r++) acc[r] = fmaf(w, xs[r * IND + t], acc[r]);
    }
#pragma unroll
    for (int r = 0; r < 8; r++) g_iou[(rowgrp * 8 + r) * 768 + col] = acc[r];
}

__device__ void st_leafgate(int bid, int tid) {
    for (int row = bid; row < 512; row += NBLK) {
        int side = row >> 8, leaf = row & 255;
        const float* base = g_iou + row * 768;
        float iv = sigm_acc(base[tid]);
        float ov = sigm_acc(base[256 + tid]);
        float uv = tanhf(base[512 + tid]);
        float c = iv * uv;
        float h = ov * tanhf(c);
        g_c[side][leaf * MEMD + tid]   = c;
        g_mat[side][leaf * MEMD + tid] = h;
    }
}

// tree level (mode 0: no-attn sides; mode 1: attended passes)
__device__ void st_tree(int bid, int tid, char* sm, int mode, int lev,
                        int offp, int off, int k,
                        const float* __restrict__ b_iouh, const float* __restrict__ b_fh) {
    int T = 2 * k;
    if (T >= 64) {
        float* h0 = (float*)sm; float* h1 = h0 + 256; float* hs = h1 + 256;
        for (int task = bid; task < T; task += NBLK) {
            int unit = (task >= k); int node = task - unit * k;
            const float *hsrc, *csrc; float *hdst, *cdst;
            if (mode == 0) { hsrc = g_mat[unit]; csrc = g_c[unit]; hdst = g_mat[unit]; cdst = g_c[unit]; }
            else { hsrc = g_hA[unit]; csrc = (lev == 1) ? g_c[1 - unit] : g_cA[unit];
                   hdst = g_hPre[unit]; cdst = g_cA[unit]; }
            int ch = (offp + 2 * node) * MEMD;
            float a = hsrc[ch + tid], b = hsrc[ch + MEMD + tid];
            h0[tid] = a; h1[tid] = b; hs[tid] = a + b;
            __syncthreads();
            float ai = 0, ao = 0, au = 0, af0 = 0, af1 = 0;
#pragma unroll 4
            for (int t = 0; t < MEMD; t++) {
                float4 w = g_Wpack[t * MEMD + tid];
                float hv = hs[t];
                ai  = fmaf(w.x, hv, ai);
                ao  = fmaf(w.y, hv, ao);
                au  = fmaf(w.z, hv, au);
                af0 = fmaf(w.w, h0[t], af0);
                af1 = fmaf(w.w, h1[t], af1);
            }
            float iv = sigm_acc(ai + b_iouh[tid]);
            float ov = sigm_acc(ao + b_iouh[256 + tid]);
            float uv = tanhf(au + b_iouh[512 + tid]);
            float f0 = sigm_acc(af0 + b_fh[tid]);
            float f1 = sigm_acc(af1 + b_fh[tid]);
            float c = iv * uv + f0 * csrc[ch + tid] + f1 * csrc[ch + MEMD + tid];
            float h = ov * tanhf(c);
            cdst[(off + node) * MEMD + tid] = c;
            hdst[(off + node) * MEMD + tid] = h;
            __syncthreads();
        }
    } else {
        // dim-split: blocks = T*8, each handles 32 output dims with 8-way e-split
        if (bid >= T * 8) return;
        float* h0 = (float*)sm; float* h1 = h0 + 256; float* red = h1 + 256; // red[8*32*5]
        int task = bid >> 3, grp = bid & 7;
        int unit = (task >= k); int node = task - unit * k;
        const float *hsrc, *csrc; float *hdst, *cdst;
        if (mode == 0) { hsrc = g_mat[unit]; csrc = g_c[unit]; hdst = g_mat[unit]; cdst = g_c[unit]; }
        else { hsrc = g_hA[unit]; csrc = (lev == 1) ? g_c[1 - unit] : g_cA[unit];
               hdst = g_hPre[unit]; cdst = g_cA[unit]; }
        int ch = (offp + 2 * node) * MEMD;
        h0[tid] = hsrc[ch + tid];
        h1[tid] = hsrc[ch + MEMD + tid];
        __syncthreads();
        int d = tid & 31, s = tid >> 5;
        int dim = grp * 32 + d;
        float ai = 0, ao = 0, au = 0, af0 = 0, af1 = 0;
        int e0 = s * 32;
#pragma unroll 8
        for (int ee = 0; ee < 32; ee++) {
            int e = e0 + ee;
            float4 w = g_Wpack[e * MEMD + dim];
            float hv = h0[e] + h1[e];
            ai  = fmaf(w.x, hv, ai);
            ao  = fmaf(w.y, hv, ao);
            au  = fmaf(w.z, hv, au);
            af0 = fmaf(w.w, h0[e], af0);
            af1 = fmaf(w.w, h1[e], af1);
        }
        float* rb = red + (s * 32 + d) * 5;
        rb[0] = ai; rb[1] = ao; rb[2] = au; rb[3] = af0; rb[4] = af1;
        __syncthreads();
        if (s == 0) {
            float A0 = 0, A1 = 0, A2 = 0, A3 = 0, A4 = 0;
#pragma unroll
            for (int ss = 0; ss < 8; ss++) {
                float* rr2 = red + (ss * 32 + d) * 5;
                A0 += rr2[0]; A1 += rr2[1]; A2 += rr2[2]; A3 += rr2[3]; A4 += rr2[4];
            }
            float iv = sigm_acc(A0 + b_iouh[dim]);
            float ov = sigm_acc(A1 + b_iouh[256 + dim]);
            float uv = tanhf(A2 + b_iouh[512 + dim]);
            float f0 = sigm_acc(A3 + b_fh[dim]);
            float f1 = sigm_acc(A4 + b_fh[dim]);
            float c = iv * uv + f0 * csrc[ch + dim] + f1 * csrc[ch + MEMD + dim];
            float h = ov * tanhf(c);
            cdst[(off + node) * MEMD + dim] = c;
            hdst[(off + node) * MEMD + dim] = h;
        }
    }
}

// proj (pb = mat@W2^T + b_attnh) + colsum(mat) per side
__device__ void st_proj(int bid, int tid, char* sm, const float* __restrict__ b_attnh) {
    if (bid < 256) {
        int side = bid >> 7; int mbase = (bid & 127) * 4;
        float* ms = (float*)sm;   // 4*256
#pragma unroll
        for (int r = 0; r < 4; r++) {
            int m = min(mbase + r, MTOT - 1);
            ms[r * 256 + tid] = g_mat[side][m * MEMD + tid];
        }
        __syncthreads();
        float ba = b_attnh[tid];
        float a0 = ba, a1 = ba, a2 = ba, a3 = ba;
#pragma unroll 4
        for (int e = 0; e < 256; e++) {
            float w = g_W2T[e * 256 + tid];
            a0 = fmaf(w, ms[e], a0);
            a1 = fmaf(w, ms[256 + e], a1);
            a2 = fmaf(w, ms[512 + e], a2);
            a3 = fmaf(w, ms[768 + e], a3);
        }
        if (mbase + 0 < MTOT) g_pb[side][(mbase + 0) * MEMD + tid] = a0;
        if (mbase + 1 < MTOT) g_pb[side][(mbase + 1) * MEMD + tid] = a1;
        if (mbase + 2 < MTOT) g_pb[side][(mbase + 2) * MEMD + tid] = a2;
        if (mbase + 3 < MTOT) g_pb[side][(mbase + 3) * MEMD + tid] = a3;
    } else if (bid < 264) {
        int s = bid - 256; int side = s >> 2; int qc = s & 3;
        int d = tid & 63; int rs = tid >> 6;
        int dim = qc * 64 + d;
        float a = 0.f;
        for (int m = rs; m < MTOT; m += 4) a += g_mat[side][m * MEMD + dim];
        float* red = (float*)sm;
        red[rs * 64 + d] = a;
        __syncthreads();
        if (rs == 0) g_colsum[side][dim] = red[d] + red[64 + d] + red[128 + d] + red[192 + d];
    }
}

// scores: raw attention scores for all rows of a level (or leaves)
__device__ void st_scores(int bid, int tid, char* sm, int leafst, int roff, int k,
                          const float* __restrict__ Wa) {
    int R = leafst ? 512 : 2 * k;
    int KS = leafst ? 1 : max(1, min(16, NBLK / R));
    int chunk = (MTOT + KS - 1) / KS;
    int total = R * KS;
    float* hrow = (float*)sm; float* hp = hrow + 256; float* wa = hp + 256;
    for (int job = bid; job < total; job += NBLK) {
        int r = job / KS, ck = job - r * KS;
        int p, n;
        if (leafst) { p = r >> 8; n = r & 255; } else { p = (r >= k); n = r - p * k; }
        int grow = roff + n;
        const float* hs_ = leafst ? g_mat[1 - p] : g_hPre[p];
        hrow[tid] = hs_[grow * MEMD + tid];
        wa[tid] = Wa[tid];
        __syncthreads();
        float acc = 0.f;
#pragma unroll 4
        for (int e = 0; e < 256; e++) acc = fmaf(g_W1T[e * 256 + tid], hrow[e], acc);
        hp[tid] = acc;
        __syncthreads();
        int warp = tid >> 5, lane = tid & 31;
        int m0 = ck * chunk, m1 = min(MTOT, m0 + chunk);
        const float* pbb = g_pb[p];
        for (int m = m0 + warp; m < m1; m += 8) {
            const float* pr = pbb + m * MEMD;
            float sc = 0.f;
#pragma unroll
            for (int dd = 0; dd < 8; dd++) {
                int d = dd * 32 + lane;
                sc = fmaf(tanh_fast(hp[d] + pr[d]), wa[d], sc);
            }
#pragma unroll
            for (int o = 16; o; o >>= 1) sc += __shfl_xor_sync(0xffffffffu, sc, o);
            if (lane == 0) g_scores[p][grow * MTOT + m] = sc;
        }
        __syncthreads();
    }
}

// softmax + combine: hA = colsum - (softmax @ mat) + h
__device__ void st_combine(int bid, int tid, char* sm, int leafst, int roff, int k) {
    int rpp = leafst ? 256 : k;
    int nbp = (rpp + 3) >> 2;
    int total = 2 * nbp;
    float* es   = (float*)sm;            // 4*512
    float* hsm  = es + 2048;             // 4*256
    float* red  = hsm + 1024;            // 256
    float* ssum = red + 256;             // 4
    float4* sp2 = (float4*)(ssum + 4);   // 4 strips * 4 rows * 64
    for (int job = bid; job < total; job += NBLK) {
        int p = job / nbp; int nbase = (job - p * nbp) * 4;
        const float* hs_ = leafst ? g_mat[1 - p] : g_hPre[p];
#pragma unroll
        for (int r = 0; r < 4; r++) {
            int n = min(nbase + r, rpp - 1);
            int grow = roff + n;
            const float* sr = g_scores[p] + grow * MTOT;
            float e0 = sr[tid];
            float e1 = (tid < 255) ? sr[256 + tid] : -1e30f;
            red[tid] = fmaxf(e0, e1);
            __syncthreads();
            for (int st = 128; st; st >>= 1) { if (tid < st) red[tid] = fmaxf(red[tid], red[tid + st]); __syncthreads(); }
            float mx = red[0];
            __syncthreads();
            float x0 = __expf(e0 - mx);
            float x1 = (tid < 255) ? __expf(e1 - mx) : 0.f;
            es[r * 512 + tid] = x0; es[r * 512 + 256 + tid] = x1;
            red[tid] = x0 + x1;
            __syncthreads();
            for (int st = 128; st; st >>= 1) { if (tid < st) red[tid] += red[tid + st]; __syncthreads(); }
            if (tid == 0) ssum[r] = red[0];
            hsm[r * 256 + tid] = hs_[grow * MEMD + tid];
            __syncthreads();
        }
        int q = tid & 63, strip = tid >> 6;
        const float4* mat4 = (const float4*)g_mat[p];
        float4 a2[4];
#pragma unroll
        for (int r = 0; r < 4; r++) a2[r] = make_float4(0, 0, 0, 0);
        for (int m = strip; m < MTOT; m += 4) {
            float4 mv = mat4[m * 64 + q];
#pragma unroll
            for (int r = 0; r < 4; r++) {
                float e = es[r * 512 + m];
                a2[r].x = fmaf(e, mv.x, a2[r].x);
                a2[r].y = fmaf(e, mv.y, a2[r].y);
                a2[r].z = fmaf(e, mv.z, a2[r].z);
                a2[r].w = fmaf(e, mv.w, a2[r].w);
            }
        }
#pragma unroll
        for (int r = 0; r < 4; r++) sp2[(strip * 4 + r) * 64 + q] = a2[r];
        __syncthreads();
        if (strip == 0) {
            const float* cs = g_colsum[p];
#pragma unroll
            for (int r = 0; r < 4; r++) {
                if (nbase + r < rpp) {
                    float4 t2 = sp2[r * 64 + q];
                    float4 tb = sp2[(4 + r) * 64 + q];
                    float4 tc = sp2[(8 + r) * 64 + q];
                    float4 td = sp2[(12 + r) * 64 + q];
                    t2.x += tb.x + tc.x + td.x;
                    t2.y += tb.y + tc.y + td.y;
                    t2.z += tb.z + tc.z + td.z;
                    t2.w += tb.w + tc.w + td.w;
                    float inv = 1.0f / ssum[r];
                    int grow = roff + nbase + r;
                    float* outp = g_hA[p] + grow * MEMD + 4 * q;
                    outp[0] = cs[4 * q + 0] - t2.x * inv + hsm[r * 256 + 4 * q + 0];
                    outp[1] = cs[4 * q + 1] - t2.y * inv + hsm[r * 256 + 4 * q + 1];
                    outp[2] = cs[4 * q + 2] - t2.z * inv + hsm[r * 256 + 4 * q + 2];
                    outp[3] = cs[4 * q + 3] - t2.w * inv + hsm[r * 256 + 4 * q + 3];
                }
            }
        }
        __syncthreads();
    }
}

__device__ void st_final(int tid, char* sm,
                         const float* __restrict__ W_wh, const float* __restrict__ b_wh,
                         const float* __restrict__ W_wp, const float* __restrict__ b_wp,
                         float* __restrict__ out) {
    float* v = (float*)sm; float* hid = v + 512;
    float lh = tanhf(g_mat[0][510 * MEMD + tid] + g_hA[1][510 * MEMD + tid]);
    float rh = tanhf(g_hA[0][510 * MEMD + tid] + g_mat[1][510 * MEMD + tid]);
    v[tid] = lh * rh;
    v[256 + tid] = fabsf(lh - rh);
    __syncthreads();
    if (tid < HIDD) {
        float a = b_wh[tid];
        for (int e = 0; e < 512; e++) a = fmaf(W_wh[tid * 512 + e], v[e], a);
        hid[tid] = sigm_acc(a);
    }
    __syncthreads();
    if (tid < 32) {
        float z[NCLS];
#pragma unroll
        for (int c = 0; c < NCLS; c++) {
            float a = 0.f;
            for (int e = tid; e < HIDD; e += 32) a = fmaf(W_wp[c * HIDD + e], hid[e], a);
#pragma unroll
            for (int o = 16; o; o >>= 1) a += __shfl_xor_sync(0xffffffffu, a, o);
            z[c] = a + b_wp[c];
        }
        if (tid == 0) {
            float mx = z[0];
#pragma unroll
            for (int c = 1; c < NCLS; c++) mx = fmaxf(mx, z[c]);
            float s = 0.f;
#pragma unroll
            for (int c = 0; c < NCLS; c++) s += expf(z[c] - mx);
            float ls = logf(s);
#pragma unroll
            for (int c = 0; c < NCLS; c++) out[c] = z[c] - mx - ls;
        }
    }
}

// ================= persistent mega kernel =================
__global__ void __launch_bounds__(256, 2)
mega_kernel(const int* l_idx, const int* r_idx, const float* emb,
            const float* W_ioux, const float* b_ioux,
            const float* W_iouh, const float* b_iouh,
            const float* W_fh, const float* b_fh,
            const float* Wa, const float* b_attnh,
            const float* W_attnh,
            const float* W_wh, const float* b_wh,
            const float* W_wp, const float* b_wp,
            float* out) {
    __shared__ __align__(16) char sm[30720];
    int bid = blockIdx.x, tid = threadIdx.x;
    int b = 0;
    const int off[9] = {0, 256, 384, 448, 480, 496, 504, 508, 510};

    st_prep(bid, tid, W_ioux, W_iouh, W_fh, W_attnh);            gbar(b++);
    st_leafgemm(bid, tid, sm, l_idx, r_idx, emb, b_ioux, b_iouh); gbar(b++);
    st_leafgate(bid, tid);                                        gbar(b++);

    for (int lev = 1; lev <= 8; lev++) {
        st_tree(bid, tid, sm, 0, lev, off[lev - 1], off[lev], LN >> lev, b_iouh, b_fh);
        gbar(b++);
    }

    st_proj(bid, tid, sm, b_attnh);            gbar(b++);
    st_scores(bid, tid, sm, 1, 0, 0, Wa);      gbar(b++);
    st_combine(bid, tid, sm, 1, 0, 0);         gbar(b++);

    for (int lev = 1; lev <= 8; lev++) {
        int k = LN >> lev;
        st_tree(bid, tid, sm, 1, lev, off[lev - 1], off[lev], k, b_iouh, b_fh); gbar(b++);
        st_scores(bid, tid, sm, 0, off[lev], k, Wa);                            gbar(b++);
        st_combine(bid, tid, sm, 0, off[lev], k);                               gbar(b++);
    }

    if (bid == 0) st_final(tid, sm, W_wh, b_wh, W_wp, b_wp, out);
}

// ================= host =================
extern "C" void kernel_launch(void* const* d_in, const int* in_sizes, int n_in,
                              void* d_out, int out_size) {
    const int*   l_idx   = (const int*)d_in[0];
    const int*   r_idx   = (const int*)d_in[1];
    const float* emb     = (const float*)d_in[2];
    const float* W_ioux  = (const float*)d_in[3];
    const float* b_ioux  = (const float*)d_in[4];
    const float* W_iouh  = (const float*)d_in[5];
    const float* b_iouh  = (const float*)d_in[6];
    // d_in[7]=W_fx, d_in[8]=b_fx unused by reference
    const float* W_fh    = (const float*)d_in[9];
    const float* b_fh    = (const float*)d_in[10];
    const float* Wa      = (const float*)d_in[11];
    const float* W_attnh = (const float*)d_in[12];
    const float* b_attnh = (const float*)d_in[13];
    const float* W_wh    = (const float*)d_in[14];
    const float* b_wh    = (const float*)d_in[15];
    const float* W_wp    = (const float*)d_in[16];
    const float* b_wp    = (const float*)d_in[17];
    float* out = (float*)d_out;

    reset_kernel<<<1, 64>>>();
    mega_kernel<<<NBLK, 256>>>(l_idx, r_idx, emb,
                               W_ioux, b_ioux, W_iouh, b_iouh, W_fh, b_fh,
                               Wa, b_attnh, W_attnh,
                               W_wh, b_wh, W_wp, b_wp, out);
}

// round 3
// speedup vs baseline: 1.2390x; 1.0102x over previous
#include <cuda_runtime.h>
#include <cuda_bf16.h>
#include <math.h>

// ---------------- problem constants ----------------
#define LN      256
#define MEMD    256
#define IND     300
#define MTOT    511
#define HIDD    128
#define NCLS    5
#define NBLK    296

// ---------------- device scratch ----------------
__device__ float  g_WxT[IND * 768];
__device__ float4 g_Wpack[MEMD * MEMD];
__device__ float  g_W1T[MEMD * MEMD];
__device__ float  g_W2T[MEMD * MEMD];
__device__ float  g_iou[512 * 768];
__device__ float  g_mat[2][MTOT * MEMD];
__device__ float  g_c  [2][MTOT * MEMD];
__device__ float  g_pb [2][MTOT * MEMD];
__device__ float  g_colsum[2][MEMD];
__device__ float  g_hA [2][MTOT * MEMD];
__device__ float  g_cA [2][MTOT * MEMD];
__device__ float  g_hPre[2][MTOT * MEMD];
__device__ float  g_scores[2][MTOT * MTOT];
__device__ int    g_bar[64];

__device__ __forceinline__ float sigm_acc(float x) { return 1.0f / (1.0f + expf(-x)); }
__device__ __forceinline__ float tanh_fast(float x) {
    float y; asm("tanh.approx.f32 %0, %1;" : "=f"(y) : "f"(x)); return y;
}

// ---------------- global software barrier ----------------
__device__ __forceinline__ void gbar(int id) {
    __syncthreads();
    if (threadIdx.x == 0) {
        __threadfence();
        atomicAdd(&g_bar[id], 1);
        while (*((volatile int*)&g_bar[id]) < NBLK) { }
        __threadfence();
    }
    __syncthreads();
}

__global__ void reset_kernel() {
    if (threadIdx.x < 64) g_bar[threadIdx.x] = 0;
}

// ================= stages =================

__device__ void st_prep(int bid, int tid,
                        const float* __restrict__ W_ioux, const float* __restrict__ W_iouh,
                        const float* __restrict__ W_fh,   const float* __restrict__ W_attnh) {
    const int N1 = IND * 768, N2 = MEMD * MEMD, N3 = MEMD * MEMD, N4 = MEMD * MEMD;
    for (int i = bid * 256 + tid; i < N1 + N2 + N3 + N4; i += NBLK * 256) {
        if (i < N1) {
            int t = i / 768, j = i - t * 768;
            g_WxT[i] = W_ioux[j * IND + t];
        } else if (i < N1 + N2) {
            int e = i - N1; int t = e >> 8, j = e & 255;
            g_Wpack[e] = make_float4(W_iouh[j * MEMD + t],
                                     W_iouh[(256 + j) * MEMD + t],
                                     W_iouh[(512 + j) * MEMD + t],
                                     W_fh[j * MEMD + t]);
        } else if (i < N1 + N2 + N3) {
            int e = i - N1 - N2; int ee = e >> 8, d = e & 255;
            g_W1T[e] = W_attnh[d * 512 + ee];
        } else {
            int e = i - N1 - N2 - N3; int ee = e >> 8, d = e & 255;
            g_W2T[e] = W_attnh[d * 512 + 256 + ee];
        }
    }
}

// leaf GEMM: 192 blocks = 64 row-groups (8 rows) x 3 col-parts (256 cols)
__device__ void st_leafgemm(int bid, int tid, char* sm,
                            const int* __restrict__ l_idx, const int* __restrict__ r_idx,
                            const float* __restrict__ emb,
                            const float* __restrict__ b_ioux, const float* __restrict__ b_iouh) {
    if (bid >= 192) return;
    float* xs = (float*)sm;                 // 8*300
    int* sidx = (int*)(sm + 2400 * 4);      // 8 ints
    int rowgrp = bid & 63;
    int part = bid >> 6;
    if (tid < 8) {
        int grow = rowgrp * 8 + tid;
        sidx[tid] = (grow >= 256) ? r_idx[grow - 256] : l_idx[grow];
    }
    __syncthreads();
    for (int e = tid; e < 8 * IND; e += 256) {
        int rr = e / IND, t = e - rr * IND;
        xs[e] = emb[(long)sidx[rr] * IND + t];
    }
    __syncthreads();
    int col = part * 256 + tid;
    float bias = b_ioux[col] + b_iouh[col];
    float acc[8];
#pragma unroll
    for (int r = 0; r < 8; r++) acc[r] = bias;
#pragma unroll 4
    for (int t = 0; t < IND; t++) {
        float w = g_WxT[t * 768 + col];
#pragma unroll
        for (int r = 0; r < 8; r++) acc[r] = fmaf(w, xs[r * IND + t], acc[r]);
    }
#pragma unroll
    for (int r = 0; r < 8; r++) g_iou[(rowgrp * 8 + r) * 768 + col] = acc[r];
}

__device__ void st_leafgate(int bid, int tid) {
    for (int row = bid; row < 512; row += NBLK) {
        int side = row >> 8, leaf = row & 255;
        const float* base = g_iou + row * 768;
        float iv = sigm_acc(base[tid]);
        float ov = sigm_acc(base[256 + tid]);
        float uv = tanhf(base[512 + tid]);
        float c = iv * uv;
        float h = ov * tanhf(c);
        g_c[side][leaf * MEMD + tid]   = c;
        g_mat[side][leaf * MEMD + tid] = h;
    }
}

// tree level (mode 0: no-attn sides; mode 1: attended passes)
__device__ void st_tree(int bid, int tid, char* sm, int mode, int lev,
                        int offp, int off, int k,
                        const float* __restrict__ b_iouh, const float* __restrict__ b_fh) {
    int T = 2 * k;
    if (T >= 64) {
        float* h0 = (float*)sm; float* h1 = h0 + 256; float* hs = h1 + 256;
        for (int task = bid; task < T; task += NBLK) {
            int unit = (task >= k); int node = task - unit * k;
            const float *hsrc, *csrc; float *hdst, *cdst;
            if (mode == 0) { hsrc = g_mat[unit]; csrc = g_c[unit]; hdst = g_mat[unit]; cdst = g_c[unit]; }
            else { hsrc = g_hA[unit]; csrc = (lev == 1) ? g_c[1 - unit] : g_cA[unit];
                   hdst = g_hPre[unit]; cdst = g_cA[unit]; }
            int ch = (offp + 2 * node) * MEMD;
            float a = hsrc[ch + tid], b = hsrc[ch + MEMD + tid];
            h0[tid] = a; h1[tid] = b; hs[tid] = a + b;
            __syncthreads();
            float ai = 0, ao = 0, au = 0, af0 = 0, af1 = 0;
#pragma unroll 4
            for (int t = 0; t < MEMD; t++) {
                float4 w = g_Wpack[t * MEMD + tid];
                float hv = hs[t];
                ai  = fmaf(w.x, hv, ai);
                ao  = fmaf(w.y, hv, ao);
                au  = fmaf(w.z, hv, au);
                af0 = fmaf(w.w, h0[t], af0);
                af1 = fmaf(w.w, h1[t], af1);
            }
            float iv = sigm_acc(ai + b_iouh[tid]);
            float ov = sigm_acc(ao + b_iouh[256 + tid]);
            float uv = tanhf(au + b_iouh[512 + tid]);
            float f0 = sigm_acc(af0 + b_fh[tid]);
            float f1 = sigm_acc(af1 + b_fh[tid]);
            float c = iv * uv + f0 * csrc[ch + tid] + f1 * csrc[ch + MEMD + tid];
            float h = ov * tanhf(c);
            cdst[(off + node) * MEMD + tid] = c;
            hdst[(off + node) * MEMD + tid] = h;
            __syncthreads();
        }
    } else {
        // dim-split: blocks = T*8, each handles 32 output dims with 8-way e-split
        if (bid >= T * 8) return;
        float* h0 = (float*)sm; float* h1 = h0 + 256; float* red = h1 + 256; // red[8*32*5]
        int task = bid >> 3, grp = bid & 7;
        int unit = (task >= k); int node = task - unit * k;
        const float *hsrc, *csrc; float *hdst, *cdst;
        if (mode == 0) { hsrc = g_mat[unit]; csrc = g_c[unit]; hdst = g_mat[unit]; cdst = g_c[unit]; }
        else { hsrc = g_hA[unit]; csrc = (lev == 1) ? g_c[1 - unit] : g_cA[unit];
               hdst = g_hPre[unit]; cdst = g_cA[unit]; }
        int ch = (offp + 2 * node) * MEMD;
        h0[tid] = hsrc[ch + tid];
        h1[tid] = hsrc[ch + MEMD + tid];
        __syncthreads();
        int d = tid & 31, s = tid >> 5;
        int dim = grp * 32 + d;
        float ai = 0, ao = 0, au = 0, af0 = 0, af1 = 0;
        int e0 = s * 32;
#pragma unroll 8
        for (int ee = 0; ee < 32; ee++) {
            int e = e0 + ee;
            float4 w = g_Wpack[e * MEMD + dim];
            float hv = h0[e] + h1[e];
            ai  = fmaf(w.x, hv, ai);
            ao  = fmaf(w.y, hv, ao);
            au  = fmaf(w.z, hv, au);
            af0 = fmaf(w.w, h0[e], af0);
            af1 = fmaf(w.w, h1[e], af1);
        }
        float* rb = red + (s * 32 + d) * 5;
        rb[0] = ai; rb[1] = ao; rb[2] = au; rb[3] = af0; rb[4] = af1;
        __syncthreads();
        if (s == 0) {
            float A0 = 0, A1 = 0, A2 = 0, A3 = 0, A4 = 0;
#pragma unroll
            for (int ss = 0; ss < 8; ss++) {
                float* rr2 = red + (ss * 32 + d) * 5;
                A0 += rr2[0]; A1 += rr2[1]; A2 += rr2[2]; A3 += rr2[3]; A4 += rr2[4];
            }
            float iv = sigm_acc(A0 + b_iouh[dim]);
            float ov = sigm_acc(A1 + b_iouh[256 + dim]);
            float uv = tanhf(A2 + b_iouh[512 + dim]);
            float f0 = sigm_acc(A3 + b_fh[dim]);
            float f1 = sigm_acc(A4 + b_fh[dim]);
            float c = iv * uv + f0 * csrc[ch + dim] + f1 * csrc[ch + MEMD + dim];
            float h = ov * tanhf(c);
            cdst[(off + node) * MEMD + dim] = c;
            hdst[(off + node) * MEMD + dim] = h;
        }
    }
}

// proj (pb = mat@W2^T + b_attnh) + colsum(mat) per side
__device__ void st_proj(int bid, int tid, char* sm, const float* __restrict__ b_attnh) {
    if (bid < 256) {
        int side = bid >> 7; int mbase = (bid & 127) * 4;
        float* ms = (float*)sm;   // 4*256
#pragma unroll
        for (int r = 0; r < 4; r++) {
            int m = min(mbase + r, MTOT - 1);
            ms[r * 256 + tid] = g_mat[side][m * MEMD + tid];
        }
        __syncthreads();
        float ba = b_attnh[tid];
        float a0 = ba, a1 = ba, a2 = ba, a3 = ba;
#pragma unroll 4
        for (int e = 0; e < 256; e++) {
            float w = g_W2T[e * 256 + tid];
            a0 = fmaf(w, ms[e], a0);
            a1 = fmaf(w, ms[256 + e], a1);
            a2 = fmaf(w, ms[512 + e], a2);
            a3 = fmaf(w, ms[768 + e], a3);
        }
        if (mbase + 0 < MTOT) g_pb[side][(mbase + 0) * MEMD + tid] = a0;
        if (mbase + 1 < MTOT) g_pb[side][(mbase + 1) * MEMD + tid] = a1;
        if (mbase + 2 < MTOT) g_pb[side][(mbase + 2) * MEMD + tid] = a2;
        if (mbase + 3 < MTOT) g_pb[side][(mbase + 3) * MEMD + tid] = a3;
    } else if (bid < 264) {
        int s = bid - 256; int side = s >> 2; int qc = s & 3;
        int d = tid & 63; int rs = tid >> 6;
        int dim = qc * 64 + d;
        float a = 0.f;
        for (int m = rs; m < MTOT; m += 4) a += g_mat[side][m * MEMD + dim];
        float* red = (float*)sm;
        red[rs * 64 + d] = a;
        __syncthreads();
        if (rs == 0) g_colsum[side][dim] = red[d] + red[64 + d] + red[128 + d] + red[192 + d];
    }
}

// scores: raw attention scores for all rows of a level (or leaves)
__device__ void st_scores(int bid, int tid, char* sm, int leafst, int roff, int k,
                          const float* __restrict__ Wa) {
    int R = leafst ? 512 : 2 * k;
    int KS = leafst ? 1 : max(1, min(16, NBLK / R));
    int chunk = (MTOT + KS - 1) / KS;
    int total = R * KS;
    float* hrow = (float*)sm; float* hp = hrow + 256; float* wa = hp + 256;
    for (int job = bid; job < total; job += NBLK) {
        int r = job / KS, ck = job - r * KS;
        int p, n;
        if (leafst) { p = r >> 8; n = r & 255; } else { p = (r >= k); n = r - p * k; }
        int grow = roff + n;
        const float* hs_ = leafst ? g_mat[1 - p] : g_hPre[p];
        hrow[tid] = hs_[grow * MEMD + tid];
        wa[tid] = Wa[tid];
        __syncthreads();
        float acc = 0.f;
#pragma unroll 4
        for (int e = 0; e < 256; e++) acc = fmaf(g_W1T[e * 256 + tid], hrow[e], acc);
        hp[tid] = acc;
        __syncthreads();
        int warp = tid >> 5, lane = tid & 31;
        int m0 = ck * chunk, m1 = min(MTOT, m0 + chunk);
        const float* pbb = g_pb[p];
        for (int m = m0 + warp; m < m1; m += 8) {
            const float* pr = pbb + m * MEMD;
            float sc = 0.f;
#pragma unroll
            for (int dd = 0; dd < 8; dd++) {
                int d = dd * 32 + lane;
                sc = fmaf(tanh_fast(hp[d] + pr[d]), wa[d], sc);
            }
#pragma unroll
            for (int o = 16; o; o >>= 1) sc += __shfl_xor_sync(0xffffffffu, sc, o);
            if (lane == 0) g_scores[p][grow * MTOT + m] = sc;
        }
        __syncthreads();
    }
}

// softmax + combine: hA = colsum - (softmax @ mat) + h
__device__ void st_combine(int bid, int tid, char* sm, int leafst, int roff, int k) {
    int rpp = leafst ? 256 : k;
    int nbp = (rpp + 3) >> 2;
    int total = 2 * nbp;
    float* es   = (float*)sm;            // 4*512
    float* hsm  = es + 2048;             // 4*256
    float* red  = hsm + 1024;            // 256
    float* ssum = red + 256;             // 4
    float4* sp2 = (float4*)(ssum + 4);   // 4 strips * 4 rows * 64
    for (int job = bid; job < total; job += NBLK) {
        int p = job / nbp; int nbase = (job - p * nbp) * 4;
        const float* hs_ = leafst ? g_mat[1 - p] : g_hPre[p];
#pragma unroll
        for (int r = 0; r < 4; r++) {
            int n = min(nbase + r, rpp - 1);
            int grow = roff + n;
            const float* sr = g_scores[p] + grow * MTOT;
            float e0 = sr[tid];
            float e1 = (tid < 255) ? sr[256 + tid] : -1e30f;
            red[tid] = fmaxf(e0, e1);
            __syncthreads();
            for (int st = 128; st; st >>= 1) { if (tid < st) red[tid] = fmaxf(red[tid], red[tid + st]); __syncthreads(); }
            float mx = red[0];
            __syncthreads();
            float x0 = __expf(e0 - mx);
            float x1 = (tid < 255) ? __expf(e1 - mx) : 0.f;
            es[r * 512 + tid] = x0; es[r * 512 + 256 + tid] = x1;
            red[tid] = x0 + x1;
            __syncthreads();
            for (int st = 128; st; st >>= 1) { if (tid < st) red[tid] += red[tid + st]; __syncthreads(); }
            if (tid == 0) ssum[r] = red[0];
            hsm[r * 256 + tid] = hs_[grow * MEMD + tid];
            __syncthreads();
        }
        int q = tid & 63, strip = tid >> 6;
        const float4* mat4 = (const float4*)g_mat[p];
        float4 a2[4];
#pragma unroll
        for (int r = 0; r < 4; r++) a2[r] = make_float4(0, 0, 0, 0);
        for (int m = strip; m < MTOT; m += 4) {
            float4 mv = mat4[m * 64 + q];
#pragma unroll
            for (int r = 0; r < 4; r++) {
                float e = es[r * 512 + m];
                a2[r].x = fmaf(e, mv.x, a2[r].x);
                a2[r].y = fmaf(e, mv.y, a2[r].y);
                a2[r].z = fmaf(e, mv.z, a2[r].z);
                a2[r].w = fmaf(e, mv.w, a2[r].w);
            }
        }
#pragma unroll
        for (int r = 0; r < 4; r++) sp2[(strip * 4 + r) * 64 + q] = a2[r];
        __syncthreads();
        if (strip == 0) {
            const float* cs = g_colsum[p];
#pragma unroll
            for (int r = 0; r < 4; r++) {
                if (nbase + r < rpp) {
                    float4 t2 = sp2[r * 64 + q];
                    float4 tb = sp2[(4 + r) * 64 + q];
                    float4 tc = sp2[(8 + r) * 64 + q];
                    float4 td = sp2[(12 + r) * 64 + q];
                    t2.x += tb.x + tc.x + td.x;
                    t2.y += tb.y + tc.y + td.y;
                    t2.z += tb.z + tc.z + td.z;
                    t2.w += tb.w + tc.w + td.w;
                    float inv = 1.0f / ssum[r];
                    int grow = roff + nbase + r;
                    float* outp = g_hA[p] + grow * MEMD + 4 * q;
                    outp[0] = cs[4 * q + 0] - t2.x * inv + hsm[r * 256 + 4 * q + 0];
                    outp[1] = cs[4 * q + 1] - t2.y * inv + hsm[r * 256 + 4 * q + 1];
                    outp[2] = cs[4 * q + 2] - t2.z * inv + hsm[r * 256 + 4 * q + 2];
                    outp[3] = cs[4 * q + 3] - t2.w * inv + hsm[r * 256 + 4 * q + 3];
                }
            }
        }
        __syncthreads();
    }
}

__device__ void st_final(int tid, char* sm,
                         const float* __restrict__ W_wh, const float* __restrict__ b_wh,
                         const float* __restrict__ W_wp, const float* __restrict__ b_wp,
                         float* __restrict__ out) {
    float* v = (float*)sm; float* hid = v + 512;
    float lh = tanhf(g_mat[0][510 * MEMD + tid] + g_hA[1][510 * MEMD + tid]);
    float rh = tanhf(g_hA[0][510 * MEMD + tid] + g_mat[1][510 * MEMD + tid]);
    v[tid] = lh * rh;
    v[256 + tid] = fabsf(lh - rh);
    __syncthreads();
    if (tid < HIDD) {
        float a = b_wh[tid];
        for (int e = 0; e < 512; e++) a = fmaf(W_wh[tid * 512 + e], v[e], a);
        hid[tid] = sigm_acc(a);
    }
    __syncthreads();
    if (tid < 32) {
        float z[NCLS];
#pragma unroll
        for (int c = 0; c < NCLS; c++) {
            float a = 0.f;
            for (int e = tid; e < HIDD; e += 32) a = fmaf(W_wp[c * HIDD + e], hid[e], a);
#pragma unroll
            for (int o = 16; o; o >>= 1) a += __shfl_xor_sync(0xffffffffu, a, o);
            z[c] = a + b_wp[c];
        }
        if (tid == 0) {
            float mx = z[0];
#pragma unroll
            for (int c = 1; c < NCLS; c++) mx = fmaxf(mx, z[c]);
            float s = 0.f;
#pragma unroll
            for (int c = 0; c < NCLS; c++) s += expf(z[c] - mx);
            float ls = logf(s);
#pragma unroll
            for (int c = 0; c < NCLS; c++) out[c] = z[c] - mx - ls;
        }
    }
}

// ================= persistent mega kernel =================
__global__ void __launch_bounds__(256, 2)
mega_kernel(const int* l_idx, const int* r_idx, const float* emb,
            const float* W_ioux, const float* b_ioux,
            const float* W_iouh, const float* b_iouh,
            const float* W_fh, const float* b_fh,
            const float* Wa, const float* b_attnh,
            const float* W_attnh,
            const float* W_wh, const float* b_wh,
            const float* W_wp, const float* b_wp,
            float* out) {
    __shared__ __align__(16) char sm[30720];
    int bid = blockIdx.x, tid = threadIdx.x;
    int b = 0;
    const int off[9] = {0, 256, 384, 448, 480, 496, 504, 508, 510};

    st_prep(bid, tid, W_ioux, W_iouh, W_fh, W_attnh);            gbar(b++);
    st_leafgemm(bid, tid, sm, l_idx, r_idx, emb, b_ioux, b_iouh); gbar(b++);
    st_leafgate(bid, tid);                                        gbar(b++);

    for (int lev = 1; lev <= 8; lev++) {
        st_tree(bid, tid, sm, 0, lev, off[lev - 1], off[lev], LN >> lev, b_iouh, b_fh);
        gbar(b++);
    }

    st_proj(bid, tid, sm, b_attnh);            gbar(b++);
    st_scores(bid, tid, sm, 1, 0, 0, Wa);      gbar(b++);
    st_combine(bid, tid, sm, 1, 0, 0);         gbar(b++);

    for (int lev = 1; lev <= 8; lev++) {
        int k = LN >> lev;
        st_tree(bid, tid, sm, 1, lev, off[lev - 1], off[lev], k, b_iouh, b_fh); gbar(b++);
        st_scores(bid, tid, sm, 0, off[lev], k, Wa);                            gbar(b++);
        st_combine(bid, tid, sm, 0, off[lev], k);                               gbar(b++);
    }

    if (bid == 0) st_final(tid, sm, W_wh, b_wh, W_wp, b_wp, out);
}

// ================= host =================
extern "C" void kernel_launch(void* const* d_in, const int* in_sizes, int n_in,
                              void* d_out, int out_size) {
    const int*   l_idx   = (const int*)d_in[0];
    const int*   r_idx   = (const int*)d_in[1];
    const float* emb     = (const float*)d_in[2];
    const float* W_ioux  = (const float*)d_in[3];
    const float* b_ioux  = (const float*)d_in[4];
    const float* W_iouh  = (const float*)d_in[5];
    const float* b_iouh  = (const float*)d_in[6];
    // d_in[7]=W_fx, d_in[8]=b_fx unused by reference
    const float* W_fh    = (const float*)d_in[9];
    const float* b_fh    = (const float*)d_in[10];
    const float* Wa      = (const float*)d_in[11];
    const float* W_attnh = (const float*)d_in[12];
    const float* b_attnh = (const float*)d_in[13];
    const float* W_wh    = (const float*)d_in[14];
    const float* b_wh    = (const float*)d_in[15];
    const float* W_wp    = (const float*)d_in[16];
    const float* b_wp    = (const float*)d_in[17];
    float* out = (float*)d_out;

    reset_kernel<<<1, 64>>>();
    mega_kernel<<<NBLK, 256>>>(l_idx, r_idx, emb,
                               W_ioux, b_ioux, W_iouh, b_iouh, W_fh, b_fh,
                               Wa, b_attnh, W_attnh,
                               W_wh, b_wh, W_wp, b_wp, out);
}